// round 13
// baseline (speedup 1.0000x reference)
#include <cuda_runtime.h>
#include <math.h>

// Problem constants
#define B_  4
#define S_  2048
#define E_  1024
#define H_  16
#define D_  64
#define M_  (B_*S_)      // 8192 rows
#define BH_ (B_*H_)      // 64 head-batches

// Scratch (device globals — no allocation allowed)
__device__ float g_q[BH_*S_*D_];   // [b,h,s,d]
__device__ float g_k[BH_*S_*D_];
__device__ float g_v[BH_*S_*D_];
__device__ float g_o[M_*E_];       // [b,s,h,d] == row-major [8192][1024]

// ---------------------------------------------------------------------------
// SGEMM: C[M x N] = A[M x 1024] @ W[1024 x N] + bias
// MODE 0: A = external (query), scatter output into g_q/g_k/g_v  (N = 3072)
// MODE 1: A = g_o, write C = d_out                                (N = 1024)
// Tiling: 128x128x16, 256 threads, 8x8 microtile.
// ---------------------------------------------------------------------------
template<int MODE>
__global__ __launch_bounds__(256)
void sgemm_kernel(const float* __restrict__ A_ext,
                  const float* __restrict__ W,
                  const float* __restrict__ bias,
                  float* __restrict__ C, int N)
{
    const int K = 1024;
    __shared__ float As[16][132];   // transposed: As[k][m]
    __shared__ float Bs[16][132];   // Bs[k][n]

    const float* A = (MODE == 0) ? A_ext : g_o;

    int tid = threadIdx.x;
    int tx = tid & 15, ty = tid >> 4;
    int m0 = blockIdx.y * 128;
    int n0 = blockIdx.x * 128;

    float acc[8][8];
#pragma unroll
    for (int i = 0; i < 8; i++)
#pragma unroll
        for (int j = 0; j < 8; j++) acc[i][j] = 0.f;

    for (int k0 = 0; k0 < K; k0 += 16) {
        // A tile: 128 rows x 16 cols = 512 float4
#pragma unroll
        for (int u = 0; u < 2; u++) {
            int idx = tid + u * 256;
            int row = idx >> 2;
            int c4  = (idx & 3) * 4;
            float4 av = *(const float4*)(A + (size_t)(m0 + row) * K + k0 + c4);
            As[c4 + 0][row] = av.x;
            As[c4 + 1][row] = av.y;
            As[c4 + 2][row] = av.z;
            As[c4 + 3][row] = av.w;
        }
        // W tile: 16 rows x 128 cols = 512 float4
#pragma unroll
        for (int u = 0; u < 2; u++) {
            int idx = tid + u * 256;
            int r  = idx >> 5;
            int c4 = (idx & 31) * 4;
            float4 bv = *(const float4*)(W + (size_t)(k0 + r) * N + n0 + c4);
            *(float4*)&Bs[r][c4] = bv;
        }
        __syncthreads();

#pragma unroll
        for (int kk = 0; kk < 16; kk++) {
            float a[8], b[8];
            *(float4*)&a[0] = *(float4*)&As[kk][ty * 4];
            *(float4*)&a[4] = *(float4*)&As[kk][ty * 4 + 64];
            *(float4*)&b[0] = *(float4*)&Bs[kk][tx * 4];
            *(float4*)&b[4] = *(float4*)&Bs[kk][tx * 4 + 64];
#pragma unroll
            for (int i = 0; i < 8; i++)
#pragma unroll
                for (int j = 0; j < 8; j++)
                    acc[i][j] = fmaf(a[i], b[j], acc[i][j]);
        }
        __syncthreads();
    }

    // epilogue
#pragma unroll
    for (int i = 0; i < 8; i++) {
        int m = m0 + ty * 4 + (i & 3) + (i >> 2) * 64;
#pragma unroll
        for (int j = 0; j < 8; j++) {
            int n = n0 + tx * 4 + (j & 3) + (j >> 2) * 64;
            float val = acc[i][j] + bias[n];
            if (MODE == 0) {
                int g = n >> 10;          // 0=q 1=k 2=v
                int e = n & 1023;
                int h = e >> 6, d = e & 63;
                int b = m >> 11, s = m & 2047;
                float* dst = (g == 0) ? g_q : (g == 1) ? g_k : g_v;
                dst[(((size_t)(b * H_ + h)) * S_ + s) * D_ + d] = val;
            } else {
                C[(size_t)m * N + n] = val;
            }
        }
    }
}

// ---------------------------------------------------------------------------
// Flash attention (fp32, online softmax).
// One block = one (b,h) head and one 128-row query tile.
// 256 threads: tx = k/d quarter-column (0..15), ty = q octet-row (0..15).
// smem: Qs_t[d][q](64x132) | Ks_t[d][k](64x68) | Vs[k][d](64x68) | Ps_t[k][q](64x132)
// ---------------------------------------------------------------------------
#define BQ   128
#define BKV  64
#define LQ   132   // padded q stride (float4-aligned)
#define LK   68    // padded k/d stride

#define SM_QS 0
#define SM_KS (64*LQ)                 // 8448
#define SM_VS (SM_KS + 64*LK)         // 12800
#define SM_PS (SM_VS + 64*LK)         // 17152
#define SM_FLASH_FLOATS (SM_PS + 64*LQ)   // 25600 floats
#define SM_FLASH_BYTES  (SM_FLASH_FLOATS * 4)  // 102400

__global__ __launch_bounds__(256)
void flash_kernel()
{
    extern __shared__ float sm[];
    float* Qs = sm + SM_QS;
    float* Ks = sm + SM_KS;
    float* Vs = sm + SM_VS;
    float* Ps = sm + SM_PS;

    int tid = threadIdx.x;
    int tx = tid & 15, ty = tid >> 4;
    int qt = blockIdx.x;          // 0..15
    int bh = blockIdx.y;          // 0..63

    const float* Qg = g_q + (size_t)bh * S_ * D_ + (size_t)qt * BQ * D_;
    const float* Kg = g_k + (size_t)bh * S_ * D_;
    const float* Vg = g_v + (size_t)bh * S_ * D_;

    // Load Q tile (128 x 64), transpose to [d][q], fold in 1/sqrt(D)=0.125
#pragma unroll
    for (int u = 0; u < 8; u++) {
        int idx = tid + u * 256;      // 0..2047 float4 units
        int r = idx >> 4;             // q row 0..127
        int c = (idx & 15) * 4;       // d col
        float4 v = *(const float4*)(Qg + r * D_ + c);
        Qs[(c + 0) * LQ + r] = v.x * 0.125f;
        Qs[(c + 1) * LQ + r] = v.y * 0.125f;
        Qs[(c + 2) * LQ + r] = v.z * 0.125f;
        Qs[(c + 3) * LQ + r] = v.w * 0.125f;
    }

    float o[8][4];
#pragma unroll
    for (int i = 0; i < 8; i++)
#pragma unroll
        for (int j = 0; j < 4; j++) o[i][j] = 0.f;
    float row_m[8], row_l[8];
#pragma unroll
    for (int i = 0; i < 8; i++) { row_m[i] = -1e30f; row_l[i] = 0.f; }

    for (int j0 = 0; j0 < S_; j0 += BKV) {
        // Load K (transposed) and V (natural): 64x64 each = 1024 float4 each
#pragma unroll
        for (int u = 0; u < 4; u++) {
            int idx = tid + u * 256;
            int r = idx >> 4;          // kv row 0..63
            int c = (idx & 15) * 4;    // d col
            float4 kv = *(const float4*)(Kg + (size_t)(j0 + r) * D_ + c);
            Ks[(c + 0) * LK + r] = kv.x;
            Ks[(c + 1) * LK + r] = kv.y;
            Ks[(c + 2) * LK + r] = kv.z;
            Ks[(c + 3) * LK + r] = kv.w;
            float4 vv = *(const float4*)(Vg + (size_t)(j0 + r) * D_ + c);
            *(float4*)&Vs[r * LK + c] = vv;
        }
        __syncthreads();

        // S = (Q/8) K^T : s[8][4], q rows = ty*8+i, k cols = tx*4+j
        float s[8][4];
#pragma unroll
        for (int i = 0; i < 8; i++)
#pragma unroll
            for (int j = 0; j < 4; j++) s[i][j] = 0.f;
#pragma unroll
        for (int kk = 0; kk < 64; kk++) {
            float qv[8], kv[4];
            *(float4*)&qv[0] = *(float4*)&Qs[kk * LQ + ty * 8];
            *(float4*)&qv[4] = *(float4*)&Qs[kk * LQ + ty * 8 + 4];
            *(float4*)&kv[0] = *(float4*)&Ks[kk * LK + tx * 4];
#pragma unroll
            for (int i = 0; i < 8; i++)
#pragma unroll
                for (int j = 0; j < 4; j++)
                    s[i][j] = fmaf(qv[i], kv[j], s[i][j]);
        }

        // online softmax per q row (reduce across tx = 16-lane half-warp)
#pragma unroll
        for (int i = 0; i < 8; i++) {
            float mx = fmaxf(fmaxf(s[i][0], s[i][1]), fmaxf(s[i][2], s[i][3]));
#pragma unroll
            for (int off = 8; off >= 1; off >>= 1)
                mx = fmaxf(mx, __shfl_xor_sync(0xffffffffu, mx, off));
            float nm = fmaxf(row_m[i], mx);
            float corr = __expf(row_m[i] - nm);
            float ps = 0.f;
#pragma unroll
            for (int j = 0; j < 4; j++) {
                s[i][j] = __expf(s[i][j] - nm);
                ps += s[i][j];
            }
#pragma unroll
            for (int off = 8; off >= 1; off >>= 1)
                ps += __shfl_xor_sync(0xffffffffu, ps, off);
            row_l[i] = row_l[i] * corr + ps;
            row_m[i] = nm;
#pragma unroll
            for (int j = 0; j < 4; j++) o[i][j] *= corr;
        }

        // stage P transposed: Ps[k][q]
#pragma unroll
        for (int i = 0; i < 8; i++)
#pragma unroll
            for (int j = 0; j < 4; j++)
                Ps[(tx * 4 + j) * LQ + ty * 8 + i] = s[i][j];
        __syncthreads();

        // O += P V : o[8][4], q rows = ty*8+i, d cols = tx*4+j
#pragma unroll
        for (int kk = 0; kk < 64; kk++) {
            float pv[8], vv[4];
            *(float4*)&pv[0] = *(float4*)&Ps[kk * LQ + ty * 8];
            *(float4*)&pv[4] = *(float4*)&Ps[kk * LQ + ty * 8 + 4];
            *(float4*)&vv[0] = *(float4*)&Vs[kk * LK + tx * 4];
#pragma unroll
            for (int i = 0; i < 8; i++)
#pragma unroll
                for (int j = 0; j < 4; j++)
                    o[i][j] = fmaf(pv[i], vv[j], o[i][j]);
        }
        __syncthreads();   // protect Ks/Vs/Ps before next iteration overwrites
    }

    // normalize and write to g_o in [b,s,h,d]
    int b = bh >> 4, h = bh & 15;
#pragma unroll
    for (int i = 0; i < 8; i++) {
        float inv = 1.0f / row_l[i];
        int q = qt * BQ + ty * 8 + i;
#pragma unroll
        for (int j = 0; j < 4; j++) {
            int d = tx * 4 + j;
            g_o[(((size_t)(b * S_ + q)) * H_ + h) * D_ + d] = o[i][j] * inv;
        }
    }
}

// ---------------------------------------------------------------------------
// Launch
// inputs: 0=query 1=key(unused) 2=value(unused) 3=W_qkv 4=b_qkv 5=W_out 6=b_out
// ---------------------------------------------------------------------------
extern "C" void kernel_launch(void* const* d_in, const int* in_sizes, int n_in,
                              void* d_out, int out_size)
{
    const float* query = (const float*)d_in[0];
    const float* W_qkv = (const float*)d_in[3];
    const float* b_qkv = (const float*)d_in[4];
    const float* W_out = (const float*)d_in[5];
    const float* b_out = (const float*)d_in[6];
    float* out = (float*)d_out;

    (void)in_sizes; (void)n_in; (void)out_size;

    cudaFuncSetAttribute(flash_kernel,
                         cudaFuncAttributeMaxDynamicSharedMemorySize,
                         SM_FLASH_BYTES);

    // 1) QKV projection + scatter
    sgemm_kernel<0><<<dim3(3072 / 128, M_ / 128), 256>>>(
        query, W_qkv, b_qkv, nullptr, 3072);

    // 2) attention
    flash_kernel<<<dim3(S_ / BQ, BH_), 256, SM_FLASH_BYTES>>>();

    // 3) output projection
    sgemm_kernel<1><<<dim3(1024 / 128, M_ / 128), 256>>>(
        nullptr, W_out, b_out, out, 1024);
}

// round 17
// speedup vs baseline: 2.0194x; 2.0194x over previous
#include <cuda_runtime.h>
#include <cuda_bf16.h>
#include <math.h>
#include <stdint.h>

// Problem constants
#define B_  4
#define S_  2048
#define E_  1024
#define H_  16
#define D_  64
#define M_  (B_*S_)      // 8192
#define BH_ (B_*H_)      // 64

// ---------------------------------------------------------------------------
// Device scratch (no allocation allowed)
// ---------------------------------------------------------------------------
__device__ __nv_bfloat16 g_qa_hi[M_*E_],    g_qa_lo[M_*E_];     // query split [m][k]
__device__ __nv_bfloat16 g_oa_hi[M_*E_],    g_oa_lo[M_*E_];     // attn out   [b,s][h*64+d]
__device__ __nv_bfloat16 g_wqkv_hi[3*E_*E_], g_wqkv_lo[3*E_*E_]; // W_qkv^T [n][k]
__device__ __nv_bfloat16 g_wout_hi[E_*E_],  g_wout_lo[E_*E_];   // W_out^T [n][k]
__device__ __nv_bfloat16 g_q_hi[BH_*S_*D_], g_q_lo[BH_*S_*D_];  // [bh][s][d], pre-scaled
__device__ __nv_bfloat16 g_k_hi[BH_*S_*D_], g_k_lo[BH_*S_*D_];  // [bh][s][d]
__device__ __nv_bfloat16 g_v_hi[BH_*S_*D_], g_v_lo[BH_*S_*D_];  // [bh][d][s] (transposed)

// ---------------------------------------------------------------------------
// Warp MMA / ldmatrix / cp.async helpers (base-ISA sm_80+, OK on sm_103)
// ---------------------------------------------------------------------------
__device__ __forceinline__ uint32_t smem_u32(const void* p) {
    uint32_t a;
    asm("{ .reg .u64 t; cvta.to.shared.u64 t, %1; cvt.u32.u64 %0, t; }" : "=r"(a) : "l"(p));
    return a;
}
// 128B-row tile swizzle: chunk (16B unit, 0..7) XOR low bits of row
__device__ __forceinline__ uint32_t swz(uint32_t row, uint32_t chunk) {
    return row * 128u + ((chunk ^ (row & 7u)) * 16u);
}
__device__ __forceinline__ void cp16(uint32_t dst, const void* src) {
    asm volatile("cp.async.cg.shared.global [%0], [%1], 16;" :: "r"(dst), "l"(src));
}
#define CP_COMMIT() asm volatile("cp.async.commit_group;" ::: "memory")
#define CP_WAIT(n)  asm volatile("cp.async.wait_group %0;" :: "n"(n) : "memory")

__device__ __forceinline__ void ldsm4(uint32_t* r, uint32_t addr) {
    asm volatile("ldmatrix.sync.aligned.m8n8.x4.shared.b16 {%0,%1,%2,%3}, [%4];"
                 : "=r"(r[0]), "=r"(r[1]), "=r"(r[2]), "=r"(r[3]) : "r"(addr));
}
__device__ __forceinline__ void mma16816(float* c, const uint32_t* a, uint32_t b0, uint32_t b1) {
    asm volatile(
        "mma.sync.aligned.m16n8k16.row.col.f32.bf16.bf16.f32 "
        "{%0,%1,%2,%3}, {%4,%5,%6,%7}, {%8,%9}, {%0,%1,%2,%3};"
        : "+f"(c[0]), "+f"(c[1]), "+f"(c[2]), "+f"(c[3])
        : "r"(a[0]), "r"(a[1]), "r"(a[2]), "r"(a[3]), "r"(b0), "r"(b1));
}
__device__ __forceinline__ uint32_t pack2(float x, float y) {
    __nv_bfloat162 t = __floats2bfloat162_rn(x, y);   // .x = low half
    return *(uint32_t*)&t;
}

// ---------------------------------------------------------------------------
// Conversion kernels (fp32 -> bf16 hi/lo split)
// ---------------------------------------------------------------------------
__global__ __launch_bounds__(256)
void convert_split(const float* __restrict__ src,
                   __nv_bfloat16* __restrict__ hi, __nv_bfloat16* __restrict__ lo, int n4)
{
    int i = blockIdx.x * 256 + threadIdx.x;
    if (i >= n4) return;
    float4 v = ((const float4*)src)[i];
    __nv_bfloat16 h0 = __float2bfloat16(v.x), h1 = __float2bfloat16(v.y);
    __nv_bfloat16 h2 = __float2bfloat16(v.z), h3 = __float2bfloat16(v.w);
    __nv_bfloat16 l0 = __float2bfloat16(v.x - __bfloat162float(h0));
    __nv_bfloat16 l1 = __float2bfloat16(v.y - __bfloat162float(h1));
    __nv_bfloat16 l2 = __float2bfloat16(v.z - __bfloat162float(h2));
    __nv_bfloat16 l3 = __float2bfloat16(v.w - __bfloat162float(h3));
    __nv_bfloat162* Hp = (__nv_bfloat162*)hi;
    __nv_bfloat162* Lp = (__nv_bfloat162*)lo;
    Hp[2*i]   = __halves2bfloat162(h0, h1);
    Hp[2*i+1] = __halves2bfloat162(h2, h3);
    Lp[2*i]   = __halves2bfloat162(l0, l1);
    Lp[2*i+1] = __halves2bfloat162(l2, l3);
}

// W [1024 x N] row-major -> transposed split [N][1024]
__global__ __launch_bounds__(256)
void transpose_split(const float* __restrict__ W,
                     __nv_bfloat16* __restrict__ hi, __nv_bfloat16* __restrict__ lo, int N)
{
    __shared__ float t[32][33];
    int n0 = blockIdx.x * 32, k0 = blockIdx.y * 32;
    int tx = threadIdx.x, ty = threadIdx.y;   // 32 x 8
#pragma unroll
    for (int r = ty; r < 32; r += 8)
        t[r][tx] = W[(size_t)(k0 + r) * N + n0 + tx];
    __syncthreads();
#pragma unroll
    for (int r = ty; r < 32; r += 8) {
        float x = t[tx][r];
        __nv_bfloat16 h = __float2bfloat16(x);
        __nv_bfloat16 l = __float2bfloat16(x - __bfloat162float(h));
        size_t off = (size_t)(n0 + r) * 1024 + k0 + tx;
        hi[off] = h; lo[off] = l;
    }
}

// ---------------------------------------------------------------------------
// bf16-split tensor-core GEMM via mma.sync
//   C[M x N] = A[M x 1024] @ B^T + bias ; A hi/lo [m][k], B hi/lo [n][k]
//   CTA 128x256, 512 thr (16 warps 4x4, warp tile 32x64), K-stage 64, 2-stage
//   cp.async pipeline. MODE 0: scatter bf16-split q/k/v. MODE 1: fp32 out.
// ---------------------------------------------------------------------------
#define G_AHI 0
#define G_ALO 16384
#define G_BHI 32768
#define G_BLO 65536
#define G_STAGE 98304
#define GEMM_SMEM (2*G_STAGE)   // 196608

template<int MODE>
__global__ __launch_bounds__(512, 1)
void tc_gemm(const __nv_bfloat16* __restrict__ Ahi, const __nv_bfloat16* __restrict__ Alo,
             const __nv_bfloat16* __restrict__ Bhi, const __nv_bfloat16* __restrict__ Blo,
             const float* __restrict__ bias, float* __restrict__ Cout)
{
    extern __shared__ char smem[];
    const uint32_t sb = smem_u32(smem);
    const int tid = threadIdx.x;
    const int lane = tid & 31, wid = tid >> 5;
    const int warp_m = wid >> 2, warp_n = wid & 3;
    const int mbase = warp_m * 32, nbase = warp_n * 64;
    const int m0 = blockIdx.y * 128;
    const int n0 = blockIdx.x * 256;

    float acc[2][8][4];
#pragma unroll
    for (int a = 0; a < 2; a++)
#pragma unroll
        for (int b = 0; b < 8; b++)
#pragma unroll
            for (int c = 0; c < 4; c++) acc[a][b][c] = 0.f;

    // stage loader: 12 cp16 per thread
    auto load_stage = [&](int s) {
        uint32_t st = sb + (s & 1) * G_STAGE;
        int k0 = s * 64;
#pragma unroll
        for (int i = 0; i < 2; i++) {
            int idx = tid + i * 512; int row = idx >> 3; int u = idx & 7;
            size_t ga = (size_t)(m0 + row) * 1024 + k0 + u * 8;
            cp16(st + G_AHI + swz(row, u), Ahi + ga);
            cp16(st + G_ALO + swz(row, u), Alo + ga);
        }
#pragma unroll
        for (int i = 0; i < 4; i++) {
            int idx = tid + i * 512; int row = idx >> 3; int u = idx & 7;
            size_t gb = (size_t)(n0 + row) * 1024 + k0 + u * 8;
            cp16(st + G_BHI + swz(row, u), Bhi + gb);
            cp16(st + G_BLO + swz(row, u), Blo + gb);
        }
    };

    load_stage(0);
    CP_COMMIT();

#pragma unroll 1
    for (int s = 0; s < 16; s++) {
        if (s + 1 < 16) { load_stage(s + 1); CP_COMMIT(); CP_WAIT(1); }
        else            { CP_WAIT(0); }
        __syncthreads();

        uint32_t st = sb + (s & 1) * G_STAGE;
        const int arow = lane & 15, achunk_hi = lane >> 4;
        const int brow = (lane & 7) + ((lane >> 4) << 3);
        const int bsel = (lane >> 3) & 1;
#pragma unroll
        for (int k = 0; k < 4; k++) {
            uint32_t ah[2][4], al[2][4];
#pragma unroll
            for (int mt = 0; mt < 2; mt++) {
                uint32_t r = mbase + mt * 16 + arow;
                uint32_t ck = 2 * k + achunk_hi;
                ldsm4(ah[mt], st + G_AHI + swz(r, ck));
                ldsm4(al[mt], st + G_ALO + swz(r, ck));
            }
#pragma unroll
            for (int bt = 0; bt < 4; bt++) {
                uint32_t bh[4], bl[4];
                uint32_t r = nbase + bt * 16 + brow;
                uint32_t ck = 2 * k + bsel;
                ldsm4(bh, st + G_BHI + swz(r, ck));
                ldsm4(bl, st + G_BLO + swz(r, ck));
#pragma unroll
                for (int mt = 0; mt < 2; mt++) {
                    mma16816(acc[mt][2*bt],   ah[mt], bh[0], bh[1]);
                    mma16816(acc[mt][2*bt],   ah[mt], bl[0], bl[1]);
                    mma16816(acc[mt][2*bt],   al[mt], bh[0], bh[1]);
                    mma16816(acc[mt][2*bt+1], ah[mt], bh[2], bh[3]);
                    mma16816(acc[mt][2*bt+1], ah[mt], bl[2], bl[3]);
                    mma16816(acc[mt][2*bt+1], al[mt], bh[2], bh[3]);
                }
            }
        }
        __syncthreads();
    }

    // epilogue
#pragma unroll
    for (int mt = 0; mt < 2; mt++) {
#pragma unroll
        for (int nt = 0; nt < 8; nt++) {
            int mA = m0 + mbase + mt * 16 + (lane >> 2);
            int n  = n0 + nbase + nt * 8 + 2 * (lane & 3);
            float b0 = __ldg(bias + n), b1 = __ldg(bias + n + 1);
            float* c = acc[mt][nt];
#pragma unroll
            for (int half = 0; half < 2; half++) {
                int m = mA + half * 8;
                float v0 = c[2*half]   + b0;
                float v1 = c[2*half+1] + b1;
                if (MODE == 0) {
                    int g = n >> 10;
                    int e = n & 1023;
                    int h = e >> 6, d = e & 63;
                    int bb = m >> 11, sq = m & 2047;
                    int bh = bb * 16 + h;
                    if (g == 0) { v0 *= 0.125f; v1 *= 0.125f; }
                    __nv_bfloat16 h0 = __float2bfloat16(v0);
                    __nv_bfloat16 h1 = __float2bfloat16(v1);
                    __nv_bfloat16 l0 = __float2bfloat16(v0 - __bfloat162float(h0));
                    __nv_bfloat16 l1 = __float2bfloat16(v1 - __bfloat162float(h1));
                    if (g < 2) {
                        __nv_bfloat16* dh = (g == 0) ? g_q_hi : g_k_hi;
                        __nv_bfloat16* dl = (g == 0) ? g_q_lo : g_k_lo;
                        size_t a = ((size_t)bh * 2048 + sq) * 64 + d;
                        *(__nv_bfloat162*)(dh + a) = __halves2bfloat162(h0, h1);
                        *(__nv_bfloat162*)(dl + a) = __halves2bfloat162(l0, l1);
                    } else {
                        size_t a = ((size_t)bh * 64 + d) * 2048 + sq;
                        g_v_hi[a] = h0; g_v_hi[a + 2048] = h1;
                        g_v_lo[a] = l0; g_v_lo[a + 2048] = l1;
                    }
                } else {
                    float2 o; o.x = v0; o.y = v1;
                    *(float2*)(Cout + (size_t)m * 1024 + n) = o;
                }
            }
        }
    }
}

// ---------------------------------------------------------------------------
// Flash attention on mma.sync. 1 CTA = (bh, 128-q tile). 8 warps x 16 q rows.
// BKV = 64 per iteration. smem 64KB -> 2 CTAs/SM.
// ---------------------------------------------------------------------------
#define F_QHI 0
#define F_QLO 16384
#define F_KHI 32768
#define F_KLO 40960
#define F_VHI 49152
#define F_VLO 57344
#define FLASH_SMEM 65536

__global__ __launch_bounds__(256, 2)
void flash_kernel()
{
    extern __shared__ char smem[];
    const uint32_t sb = smem_u32(smem);
    const int tid = threadIdx.x;
    const int lane = tid & 31, w = tid >> 5;
    const int qt = blockIdx.x;       // 0..15
    const int bh = blockIdx.y;       // 0..63

    const size_t qoff = ((size_t)bh * 2048 + qt * 128) * 64;
    // Q tile load (hi+lo), 8 cp16/thread
#pragma unroll
    for (int i = 0; i < 4; i++) {
        int idx = tid + i * 256; int row = idx >> 3; int u = idx & 7;
        cp16(sb + F_QHI + swz(row, u), g_q_hi + qoff + (size_t)row * 64 + u * 8);
        cp16(sb + F_QLO + swz(row, u), g_q_lo + qoff + (size_t)row * 64 + u * 8);
    }
    CP_COMMIT();

    float oacc[8][4];
#pragma unroll
    for (int t = 0; t < 8; t++)
#pragma unroll
        for (int c = 0; c < 4; c++) oacc[t][c] = 0.f;
    float row_m0 = -1e30f, row_m1 = -1e30f, row_l0 = 0.f, row_l1 = 0.f;

    const int arow = 16 * w + (lane & 15);
    const int achunk_hi = lane >> 4;
    const int brow = (lane & 7) + ((lane >> 4) << 3);
    const int bsel = (lane >> 3) & 1;

#pragma unroll 1
    for (int it = 0; it < 32; it++) {
        int j0 = it * 64;
        // K tile [64 j][64 d], V^T tile [64 d][64 j]: 8 cp16/thread
#pragma unroll
        for (int i = 0; i < 2; i++) {
            int idx = tid + i * 256; int row = idx >> 3; int u = idx & 7;
            size_t ka = ((size_t)bh * 2048 + j0 + row) * 64 + u * 8;
            cp16(sb + F_KHI + swz(row, u), g_k_hi + ka);
            cp16(sb + F_KLO + swz(row, u), g_k_lo + ka);
            size_t va = ((size_t)bh * 64 + row) * 2048 + j0 + u * 8;
            cp16(sb + F_VHI + swz(row, u), g_v_hi + va);
            cp16(sb + F_VLO + swz(row, u), g_v_lo + va);
        }
        CP_COMMIT();
        CP_WAIT(0);
        __syncthreads();

        // ---- S = Q K^T (scaled Q) ----
        float sacc[8][4];
#pragma unroll
        for (int t = 0; t < 8; t++)
#pragma unroll
            for (int c = 0; c < 4; c++) sacc[t][c] = 0.f;
#pragma unroll
        for (int k = 0; k < 4; k++) {
            uint32_t qh[4], ql[4];
            uint32_t ck = 2 * k + achunk_hi;
            ldsm4(qh, sb + F_QHI + swz(arow, ck));
            ldsm4(ql, sb + F_QLO + swz(arow, ck));
            uint32_t bck = 2 * k + bsel;
#pragma unroll
            for (int bt = 0; bt < 4; bt++) {
                uint32_t kh[4], kl[4];
                uint32_t r = bt * 16 + brow;
                ldsm4(kh, sb + F_KHI + swz(r, bck));
                ldsm4(kl, sb + F_KLO + swz(r, bck));
                mma16816(sacc[2*bt],   qh, kh[0], kh[1]);
                mma16816(sacc[2*bt],   qh, kl[0], kl[1]);
                mma16816(sacc[2*bt],   ql, kh[0], kh[1]);
                mma16816(sacc[2*bt+1], qh, kh[2], kh[3]);
                mma16816(sacc[2*bt+1], qh, kl[2], kl[3]);
                mma16816(sacc[2*bt+1], ql, kh[2], kh[3]);
            }
        }

        // ---- online softmax (rows r0 = c0/c1, r1 = c2/c3; quad = same row) ----
        float mx0 = sacc[0][0], mx1 = sacc[0][2];
#pragma unroll
        for (int t = 0; t < 8; t++) {
            mx0 = fmaxf(mx0, fmaxf(sacc[t][0], sacc[t][1]));
            mx1 = fmaxf(mx1, fmaxf(sacc[t][2], sacc[t][3]));
        }
        mx0 = fmaxf(mx0, __shfl_xor_sync(0xffffffffu, mx0, 1));
        mx0 = fmaxf(mx0, __shfl_xor_sync(0xffffffffu, mx0, 2));
        mx1 = fmaxf(mx1, __shfl_xor_sync(0xffffffffu, mx1, 1));
        mx1 = fmaxf(mx1, __shfl_xor_sync(0xffffffffu, mx1, 2));
        float nm0 = fmaxf(row_m0, mx0), nm1 = fmaxf(row_m1, mx1);
        float corr0 = __expf(row_m0 - nm0), corr1 = __expf(row_m1 - nm1);
        float sum0 = 0.f, sum1 = 0.f;
#pragma unroll
        for (int t = 0; t < 8; t++) {
            sacc[t][0] = __expf(sacc[t][0] - nm0); sum0 += sacc[t][0];
            sacc[t][1] = __expf(sacc[t][1] - nm0); sum0 += sacc[t][1];
            sacc[t][2] = __expf(sacc[t][2] - nm1); sum1 += sacc[t][2];
            sacc[t][3] = __expf(sacc[t][3] - nm1); sum1 += sacc[t][3];
        }
        sum0 += __shfl_xor_sync(0xffffffffu, sum0, 1);
        sum0 += __shfl_xor_sync(0xffffffffu, sum0, 2);
        sum1 += __shfl_xor_sync(0xffffffffu, sum1, 1);
        sum1 += __shfl_xor_sync(0xffffffffu, sum1, 2);
        row_l0 = row_l0 * corr0 + sum0;
        row_l1 = row_l1 * corr1 + sum1;
        row_m0 = nm0; row_m1 = nm1;
#pragma unroll
        for (int t = 0; t < 8; t++) {
            oacc[t][0] *= corr0; oacc[t][1] *= corr0;
            oacc[t][2] *= corr1; oacc[t][3] *= corr1;
        }

        // ---- O += P V (P split hi/lo built in-register, FA2 layout identity) ----
#pragma unroll
        for (int kt = 0; kt < 4; kt++) {
            float p00 = sacc[2*kt][0],   p01 = sacc[2*kt][1];
            float p10 = sacc[2*kt][2],   p11 = sacc[2*kt][3];
            float p20 = sacc[2*kt+1][0], p21 = sacc[2*kt+1][1];
            float p30 = sacc[2*kt+1][2], p31 = sacc[2*kt+1][3];
            uint32_t ph[4], pl[4];
            ph[0] = pack2(p00, p01); ph[1] = pack2(p10, p11);
            ph[2] = pack2(p20, p21); ph[3] = pack2(p30, p31);
            __nv_bfloat162 t0 = *(__nv_bfloat162*)&ph[0];
            __nv_bfloat162 t1 = *(__nv_bfloat162*)&ph[1];
            __nv_bfloat162 t2 = *(__nv_bfloat162*)&ph[2];
            __nv_bfloat162 t3 = *(__nv_bfloat162*)&ph[3];
            pl[0] = pack2(p00 - __bfloat162float(t0.x), p01 - __bfloat162float(t0.y));
            pl[1] = pack2(p10 - __bfloat162float(t1.x), p11 - __bfloat162float(t1.y));
            pl[2] = pack2(p20 - __bfloat162float(t2.x), p21 - __bfloat162float(t2.y));
            pl[3] = pack2(p30 - __bfloat162float(t3.x), p31 - __bfloat162float(t3.y));
            uint32_t bck = 2 * kt + bsel;
#pragma unroll
            for (int bt = 0; bt < 4; bt++) {
                uint32_t vh[4], vl[4];
                uint32_t r = bt * 16 + brow;
                ldsm4(vh, sb + F_VHI + swz(r, bck));
                ldsm4(vl, sb + F_VLO + swz(r, bck));
                mma16816(oacc[2*bt],   ph, vh[0], vh[1]);
                mma16816(oacc[2*bt],   ph, vl[0], vl[1]);
                mma16816(oacc[2*bt],   pl, vh[0], vh[1]);
                mma16816(oacc[2*bt+1], ph, vh[2], vh[3]);
                mma16816(oacc[2*bt+1], ph, vl[2], vl[3]);
                mma16816(oacc[2*bt+1], pl, vh[2], vh[3]);
            }
        }
        __syncthreads();   // all warps done with K/V smem before next load
    }

    // ---- epilogue: normalize, split to bf16 hi/lo, write [b,s][h*64+d] ----
    int bb = bh >> 4, h = bh & 15;
    float inv0 = 1.f / row_l0, inv1 = 1.f / row_l1;
    int q0 = qt * 128 + 16 * w + (lane >> 2);
#pragma unroll
    for (int t = 0; t < 8; t++) {
        int d = 8 * t + 2 * (lane & 3);
#pragma unroll
        for (int half = 0; half < 2; half++) {
            float v0 = oacc[t][2*half]   * (half ? inv1 : inv0);
            float v1 = oacc[t][2*half+1] * (half ? inv1 : inv0);
            int m = bb * 2048 + q0 + half * 8;
            size_t a = (size_t)m * 1024 + h * 64 + d;
            __nv_bfloat16 h0 = __float2bfloat16(v0);
            __nv_bfloat16 h1 = __float2bfloat16(v1);
            __nv_bfloat16 l0 = __float2bfloat16(v0 - __bfloat162float(h0));
            __nv_bfloat16 l1 = __float2bfloat16(v1 - __bfloat162float(h1));
            *(__nv_bfloat162*)(g_oa_hi + a) = __halves2bfloat162(h0, h1);
            *(__nv_bfloat162*)(g_oa_lo + a) = __halves2bfloat162(l0, l1);
        }
    }
}

// ---------------------------------------------------------------------------
// Launch: 0=query 1=key(unused) 2=value(unused) 3=W_qkv 4=b_qkv 5=W_out 6=b_out
// ---------------------------------------------------------------------------
extern "C" void kernel_launch(void* const* d_in, const int* in_sizes, int n_in,
                              void* d_out, int out_size)
{
    const float* query = (const float*)d_in[0];
    const float* W_qkv = (const float*)d_in[3];
    const float* b_qkv = (const float*)d_in[4];
    const float* W_out = (const float*)d_in[5];
    const float* b_out = (const float*)d_in[6];
    float* out = (float*)d_out;
    (void)in_sizes; (void)n_in; (void)out_size;

    cudaFuncSetAttribute(tc_gemm<0>,   cudaFuncAttributeMaxDynamicSharedMemorySize, GEMM_SMEM);
    cudaFuncSetAttribute(tc_gemm<1>,   cudaFuncAttributeMaxDynamicSharedMemorySize, GEMM_SMEM);
    cudaFuncSetAttribute(flash_kernel, cudaFuncAttributeMaxDynamicSharedMemorySize, FLASH_SMEM);

    __nv_bfloat16 *qa_hi, *qa_lo, *oa_hi, *oa_lo, *wq_hi, *wq_lo, *wo_hi, *wo_lo;
    cudaGetSymbolAddress((void**)&qa_hi, g_qa_hi);
    cudaGetSymbolAddress((void**)&qa_lo, g_qa_lo);
    cudaGetSymbolAddress((void**)&oa_hi, g_oa_hi);
    cudaGetSymbolAddress((void**)&oa_lo, g_oa_lo);
    cudaGetSymbolAddress((void**)&wq_hi, g_wqkv_hi);
    cudaGetSymbolAddress((void**)&wq_lo, g_wqkv_lo);
    cudaGetSymbolAddress((void**)&wo_hi, g_wout_hi);
    cudaGetSymbolAddress((void**)&wo_lo, g_wout_lo);

    // 1) input conversions
    convert_split<<<(M_*E_/4 + 255)/256, 256>>>(query, qa_hi, qa_lo, M_*E_/4);
    transpose_split<<<dim3(3*E_/32, E_/32), dim3(32, 8)>>>(W_qkv, wq_hi, wq_lo, 3*E_);
    transpose_split<<<dim3(E_/32,  E_/32), dim3(32, 8)>>>(W_out, wo_hi, wo_lo, E_);

    // 2) QKV projection -> bf16-split q/k/v (q pre-scaled, v transposed)
    tc_gemm<0><<<dim3(3*E_/256, M_/128), 512, GEMM_SMEM>>>(
        qa_hi, qa_lo, wq_hi, wq_lo, b_qkv, nullptr);

    // 3) flash attention -> bf16-split attn output
    flash_kernel<<<dim3(S_/128, BH_), 256, FLASH_SMEM>>>();

    // 4) output projection -> fp32 d_out
    tc_gemm<1><<<dim3(E_/256, M_/128), 512, GEMM_SMEM>>>(
        oa_hi, oa_lo, wo_hi, wo_lo, b_out, out);
}